// round 8
// baseline (speedup 1.0000x reference)
#include <cuda_runtime.h>

// DiscriminatorLoss: out = mean( (s==other_s ? +1 : -1) * x ), N = 33554432.
// HBM-bound streaming reduction (~402 MB read, ~6.5 TB/s achieved).
// Main loop = R6's proven body (2-way unroll, __ldcs streaming vec4 loads,
// 31 regs) but grid = 1216 CTAs = 152 SMs x 8 CTAs (one exactly-full wave):
// per-SM max work drops from 7 CTAs x 32 iters = 224 units (1024-CTA config,
// 112 SMs carry 7) to 8 x 27 = 216 units. Tests whether SM-fill beats the
// clean power-of-two per-thread iteration count.
// Epilogue: deterministic 64-bit fixed-point atomicAdd (bit-identical every
// replay); last-ticket block resets the accumulator (graph-replay safe).

#define RBLOCKS 1216          // 152 SMs * 8 CTAs/SM
#define RTHREADS 256

__device__ long long    g_accum;    // zero-initialized; reset via atomicExch
__device__ unsigned int g_ticket;   // zero-initialized; wraps back to 0

#define FXSCALE 4294967296.0
#define FXINV   (1.0 / 4294967296.0)

__global__ __launch_bounds__(RTHREADS)
void disc_loss_fused(const int* __restrict__ s,
                     const int* __restrict__ o,
                     const float* __restrict__ x,
                     int n4, float inv_n,
                     float* __restrict__ out)
{
    const int4*   s4 = reinterpret_cast<const int4*>(s);
    const int4*   o4 = reinterpret_cast<const int4*>(o);
    const float4* x4 = reinterpret_cast<const float4*>(x);

    float acc = 0.0f;
    const int stride = gridDim.x * blockDim.x;
    int i = blockIdx.x * blockDim.x + threadIdx.x;

    // 2-way unrolled grid-stride loop: 6 independent 128-bit streaming loads
    // in flight per body.
    for (; i + stride < n4; i += 2 * stride) {
        int4   sa = __ldcs(&s4[i]);
        int4   oa = __ldcs(&o4[i]);
        int4   sb = __ldcs(&s4[i + stride]);
        int4   ob = __ldcs(&o4[i + stride]);
        float4 xa = __ldcs(&x4[i]);
        float4 xb = __ldcs(&x4[i + stride]);

        acc += (sa.x == oa.x) ? xa.x : -xa.x;
        acc += (sa.y == oa.y) ? xa.y : -xa.y;
        acc += (sa.z == oa.z) ? xa.z : -xa.z;
        acc += (sa.w == oa.w) ? xa.w : -xa.w;
        acc += (sb.x == ob.x) ? xb.x : -xb.x;
        acc += (sb.y == ob.y) ? xb.y : -xb.y;
        acc += (sb.z == ob.z) ? xb.z : -xb.z;
        acc += (sb.w == ob.w) ? xb.w : -xb.w;
    }
    for (; i < n4; i += stride) {
        int4   sv = __ldcs(&s4[i]);
        int4   ov = __ldcs(&o4[i]);
        float4 xv = __ldcs(&x4[i]);
        acc += (sv.x == ov.x) ? xv.x : -xv.x;
        acc += (sv.y == ov.y) ? xv.y : -xv.y;
        acc += (sv.z == ov.z) ? xv.z : -xv.z;
        acc += (sv.w == ov.w) ? xv.w : -xv.w;
    }

    // Block reduce
    #pragma unroll
    for (int off = 16; off > 0; off >>= 1)
        acc += __shfl_xor_sync(0xffffffffu, acc, off);

    __shared__ float warp_sums[RTHREADS / 32];
    if ((threadIdx.x & 31) == 0)
        warp_sums[threadIdx.x >> 5] = acc;
    __syncthreads();

    if (threadIdx.x == 0) {
        float v = warp_sums[0];
        #pragma unroll
        for (int w = 1; w < RTHREADS / 32; w++)
            v += warp_sums[w];

        // Deterministic fixed-point accumulation (integer adds associative).
        long long q = llrint((double)v * FXSCALE);
        atomicAdd((unsigned long long*)&g_accum, (unsigned long long)q);
        __threadfence();

        // atomicInc wraps: old==RBLOCKS-1 -> 0 (self-resets per replay).
        unsigned int t = atomicInc(&g_ticket, RBLOCKS - 1u);
        if (t == RBLOCKS - 1u) {
            __threadfence();
            long long total =
                (long long)atomicExch((unsigned long long*)&g_accum, 0ull);
            out[0] = (float)((double)total * FXINV * (double)inv_n);
        }
    }
}

extern "C" void kernel_launch(void* const* d_in, const int* in_sizes, int n_in,
                              void* d_out, int out_size)
{
    const int*   s = (const int*)d_in[0];
    const int*   o = (const int*)d_in[1];
    const float* x = (const float*)d_in[2];
    float* out = (float*)d_out;

    const int n  = in_sizes[0];
    const int n4 = n >> 2;

    disc_loss_fused<<<RBLOCKS, RTHREADS>>>(s, o, x, n4, 1.0f / (float)n, out);
}

// round 9
// speedup vs baseline: 1.0367x; 1.0367x over previous
#include <cuda_runtime.h>

// DiscriminatorLoss: out = mean( (s==other_s ? +1 : -1) * x ), N = 33554432.
// HBM/LTS-bound streaming reduction (~402 MB read; 6.52 TB/s ~ 94% of the
// LTS path-independent cap). FINAL configuration, re-benched for variance:
//  - 1024 CTAs x 256 thr: n4/stride == 32 exactly -> 16 clean 2-way bodies,
//    zero tail, perfectly even per-thread work. (1216-CTA full-fill tested
//    twice, loses ~2.7us to ragged division despite occ 96%.)
//  - 2-way unroll, 6 independent LDG.128 in flight, 31 regs (8 CTAs/SM).
//  - __ldcs evict-first streaming loads (single-touch data; +2.1us win).
//  - Last-arriving block (self-resetting atomicInc ticket) folds partials in
//    fixed order -> deterministic, graph-replay safe.

#define RBLOCKS 1024
#define RTHREADS 256

__device__ float g_partials[RBLOCKS];
__device__ unsigned int g_ticket;   // zero-initialized; wraps back to 0

__global__ __launch_bounds__(RTHREADS)
void disc_loss_fused(const int* __restrict__ s,
                     const int* __restrict__ o,
                     const float* __restrict__ x,
                     int n4, float inv_n,
                     float* __restrict__ out)
{
    const int4*   s4 = reinterpret_cast<const int4*>(s);
    const int4*   o4 = reinterpret_cast<const int4*>(o);
    const float4* x4 = reinterpret_cast<const float4*>(x);

    float acc = 0.0f;
    const int stride = gridDim.x * blockDim.x;
    int i = blockIdx.x * blockDim.x + threadIdx.x;

    // 2-way unrolled grid-stride loop: 6 independent 128-bit streaming loads
    // in flight per body. On the bench shape n4 == 32*stride: 16 clean bodies,
    // no tail.
    for (; i + stride < n4; i += 2 * stride) {
        int4   sa = __ldcs(&s4[i]);
        int4   oa = __ldcs(&o4[i]);
        int4   sb = __ldcs(&s4[i + stride]);
        int4   ob = __ldcs(&o4[i + stride]);
        float4 xa = __ldcs(&x4[i]);
        float4 xb = __ldcs(&x4[i + stride]);

        acc += (sa.x == oa.x) ? xa.x : -xa.x;
        acc += (sa.y == oa.y) ? xa.y : -xa.y;
        acc += (sa.z == oa.z) ? xa.z : -xa.z;
        acc += (sa.w == oa.w) ? xa.w : -xa.w;
        acc += (sb.x == ob.x) ? xb.x : -xb.x;
        acc += (sb.y == ob.y) ? xb.y : -xb.y;
        acc += (sb.z == ob.z) ? xb.z : -xb.z;
        acc += (sb.w == ob.w) ? xb.w : -xb.w;
    }
    for (; i < n4; i += stride) {
        int4   sv = __ldcs(&s4[i]);
        int4   ov = __ldcs(&o4[i]);
        float4 xv = __ldcs(&x4[i]);
        acc += (sv.x == ov.x) ? xv.x : -xv.x;
        acc += (sv.y == ov.y) ? xv.y : -xv.y;
        acc += (sv.z == ov.z) ? xv.z : -xv.z;
        acc += (sv.w == ov.w) ? xv.w : -xv.w;
    }

    // Block reduce
    #pragma unroll
    for (int off = 16; off > 0; off >>= 1)
        acc += __shfl_xor_sync(0xffffffffu, acc, off);

    __shared__ float warp_sums[RTHREADS / 32];
    __shared__ bool  s_last;
    if ((threadIdx.x & 31) == 0)
        warp_sums[threadIdx.x >> 5] = acc;
    __syncthreads();

    if (threadIdx.x < 32) {
        float v = (threadIdx.x < (RTHREADS / 32)) ? warp_sums[threadIdx.x] : 0.0f;
        #pragma unroll
        for (int off = (RTHREADS / 64); off > 0; off >>= 1)
            v += __shfl_xor_sync(0xffffffffu, v, off);
        if (threadIdx.x == 0) {
            g_partials[blockIdx.x] = v;
            __threadfence();
            // atomicInc wraps: old==RBLOCKS-1 -> 0 (self-resets per replay).
            unsigned int t = atomicInc(&g_ticket, RBLOCKS - 1u);
            s_last = (t == RBLOCKS - 1u);
        }
    }
    __syncthreads();

    if (s_last) {
        // Fixed-order fold of all partials -> deterministic output.
        const volatile float* p = g_partials;
        float v = p[threadIdx.x]
                + p[threadIdx.x + 256]
                + p[threadIdx.x + 512]
                + p[threadIdx.x + 768];

        #pragma unroll
        for (int off = 16; off > 0; off >>= 1)
            v += __shfl_xor_sync(0xffffffffu, v, off);

        if ((threadIdx.x & 31) == 0)
            warp_sums[threadIdx.x >> 5] = v;
        __syncthreads();

        if (threadIdx.x < 32) {
            float t = (threadIdx.x < (RTHREADS / 32)) ? warp_sums[threadIdx.x] : 0.0f;
            #pragma unroll
            for (int off = (RTHREADS / 64); off > 0; off >>= 1)
                t += __shfl_xor_sync(0xffffffffu, t, off);
            if (threadIdx.x == 0)
                out[0] = t * inv_n;
        }
    }
}

extern "C" void kernel_launch(void* const* d_in, const int* in_sizes, int n_in,
                              void* d_out, int out_size)
{
    const int*   s = (const int*)d_in[0];
    const int*   o = (const int*)d_in[1];
    const float* x = (const float*)d_in[2];
    float* out = (float*)d_out;

    const int n  = in_sizes[0];
    const int n4 = n >> 2;

    disc_loss_fused<<<RBLOCKS, RTHREADS>>>(s, o, x, n4, 1.0f / (float)n, out);
}